// round 1
// baseline (speedup 1.0000x reference)
#include <cuda_runtime.h>
#include <math.h>

#define LEN    8192
#define LOG2L  13
#define NT     512
#define HN     256
#define BN     8
#define NBF    (LEN/2)       // 4096 butterflies per stage
#define BPT    (NBF/NT)      // 8 butterflies per thread per stage
#define EPT    (LEN/NT)      // 16 elements per thread for load/store

// Scratch: K spectra (bit-reversed order) + twiddle table
__device__ float2 g_khat[(size_t)HN * LEN];   // 16 MB
__device__ float2 g_tw[NBF];                  // 32 KB: exp(-2*pi*i*j/LEN), j in [0, LEN/2)

__device__ __forceinline__ float2 cmul(float2 a, float2 b) {
    return make_float2(a.x * b.x - a.y * b.y, a.x * b.y + a.y * b.x);
}

__global__ void tw_kernel() {
    int j = blockIdx.x * blockDim.x + threadIdx.x;
    if (j < NBF) {
        double ang = -2.0 * 3.141592653589793238462643 * (double)j / (double)LEN;
        g_tw[j] = make_float2((float)cos(ang), (float)sin(ang));
    }
}

// Forward DIF radix-2 FFT in smem. Input natural order, output bit-reversed.
__device__ void fft_fwd_dif(float2* s, int tid) {
    #pragma unroll
    for (int stage = LOG2L; stage >= 1; --stage) {
        const int half = 1 << (stage - 1);
        const int tsh  = LOG2L - stage;  // twiddle stride shift
        __syncthreads();
        #pragma unroll
        for (int i = 0; i < BPT; ++i) {
            int j   = tid + i * NT;
            int pos = j & (half - 1);
            int i0  = 2 * j - pos;
            int i1  = i0 + half;
            float2 a = s[i0], b = s[i1];
            float2 sum = make_float2(a.x + b.x, a.y + b.y);
            float2 dif = make_float2(a.x - b.x, a.y - b.y);
            float2 w = g_tw[pos << tsh];
            s[i0] = sum;
            s[i1] = cmul(dif, w);
        }
    }
    __syncthreads();
}

// Inverse DIT radix-2 FFT in smem (conjugate twiddles, unscaled).
// Input bit-reversed order, output natural order.
__device__ void fft_inv_dit(float2* s, int tid) {
    #pragma unroll
    for (int stage = 1; stage <= LOG2L; ++stage) {
        const int half = 1 << (stage - 1);
        const int tsh  = LOG2L - stage;
        __syncthreads();
        #pragma unroll
        for (int i = 0; i < BPT; ++i) {
            int j   = tid + i * NT;
            int pos = j & (half - 1);
            int i0  = 2 * j - pos;
            int i1  = i0 + half;
            float2 w = g_tw[pos << tsh];
            w.y = -w.y;                      // conjugate for inverse
            float2 b = cmul(s[i1], w);
            float2 a = s[i0];
            s[i0] = make_float2(a.x + b.x, a.y + b.y);
            s[i1] = make_float2(a.x - b.x, a.y - b.y);
        }
    }
    __syncthreads();
}

// One block per kernel-channel h: K_hat[h] = DIF-FFT(K[h]) stored bit-reversed.
__global__ void __launch_bounds__(NT) khat_kernel(const float* __restrict__ K) {
    extern __shared__ float2 s[];
    const int h = blockIdx.x;
    const int tid = threadIdx.x;
    const float* krow = K + (size_t)h * LEN;
    #pragma unroll
    for (int i = 0; i < EPT; ++i) {
        int idx = tid + i * NT;
        s[idx] = make_float2(krow[idx], 0.0f);
    }
    fft_fwd_dif(s, tid);
    float2* out = g_khat + (size_t)h * LEN;
    #pragma unroll
    for (int i = 0; i < EPT; ++i) {
        int idx = tid + i * NT;
        out[idx] = s[idx];
    }
}

// One block per (batch-pair, h): z = u[2b] + i*u[2b+1]; Z = FFT(z); W = Z * Khat;
// w = IFFT(W)/L; y[2b] = tanh(Re(w) + D*u[2b]); y[2b+1] = tanh(Im(w) + D*u[2b+1]).
__global__ void __launch_bounds__(NT) conv_kernel(const float* __restrict__ u,
                                                  const float* __restrict__ D,
                                                  float* __restrict__ y) {
    extern __shared__ float2 s[];
    const int bid = blockIdx.x;          // [0, (BN/2)*HN)
    const int h   = bid & (HN - 1);
    const int bp  = bid >> 8;            // batch pair index
    const int tid = threadIdx.x;

    const size_t row0 = ((size_t)(2 * bp) * HN + h) * LEN;
    const size_t row1 = row0 + (size_t)HN * LEN;   // (2bp+1, h) row
    const float* u0 = u + row0;
    const float* u1 = u + row1;

    // Load packed complex row
    #pragma unroll
    for (int i = 0; i < EPT; ++i) {
        int idx = tid + i * NT;
        s[idx] = make_float2(u0[idx], u1[idx]);
    }

    fft_fwd_dif(s, tid);

    // Pointwise multiply by K spectrum (both bit-reversed: consistent)
    const float2* kh = g_khat + (size_t)h * LEN;
    #pragma unroll
    for (int i = 0; i < EPT; ++i) {
        int idx = tid + i * NT;
        s[idx] = cmul(s[idx], kh[idx]);
    }

    fft_inv_dit(s, tid);

    const float dv = D[h];
    const float invL = 1.0f / (float)LEN;
    float* y0 = y + row0;
    float* y1 = y + row1;
    #pragma unroll
    for (int i = 0; i < EPT; ++i) {
        int idx = tid + i * NT;
        float2 w = s[idx];
        y0[idx] = tanhf(w.x * invL + dv * u0[idx]);
        y1[idx] = tanhf(w.y * invL + dv * u1[idx]);
    }
}

extern "C" void kernel_launch(void* const* d_in, const int* in_sizes, int n_in,
                              void* d_out, int out_size) {
    const float* u = (const float*)d_in[0];   // (B,H,L)
    const float* K = (const float*)d_in[1];   // (H,L)
    const float* D = (const float*)d_in[2];   // (H,)
    float* y = (float*)d_out;                 // (B,H,L)

    const int smem = LEN * sizeof(float2);    // 64 KB
    cudaFuncSetAttribute(khat_kernel, cudaFuncAttributeMaxDynamicSharedMemorySize, smem);
    cudaFuncSetAttribute(conv_kernel, cudaFuncAttributeMaxDynamicSharedMemorySize, smem);

    tw_kernel<<<(NBF + NT - 1) / NT, NT>>>();
    khat_kernel<<<HN, NT, smem>>>(K);
    conv_kernel<<<(BN / 2) * HN, NT, smem>>>(u, D, y);
}

// round 2
// speedup vs baseline: 1.5881x; 1.5881x over previous
#include <cuda_runtime.h>
#include <math.h>

#define LEN    8192
#define LOG2L  13
#define NT     512
#define HN     256
#define BN     8
#define EPT    16                  // elements per thread
#define PD(i)  ((i) + ((i) >> 5))  // smem padding: +1 float2 per 32

// K spectra in (thread,reg) layout of the forward FFT + compact twiddle tables
__device__ float2 g_khat[(size_t)HN * LEN];   // 16 MB
__device__ float2 g_tw[LEN / 2];              // exp(-2*pi*i*j/8192), j<4096
__device__ float2 g_tw16[256];                // exp(-2*pi*i*16j/8192)
__device__ float2 g_tw256[16];                // exp(-2*pi*i*256j/8192)

__device__ __forceinline__ float2 cadd(float2 a, float2 b){ return make_float2(a.x+b.x, a.y+b.y); }
__device__ __forceinline__ float2 csub(float2 a, float2 b){ return make_float2(a.x-b.x, a.y-b.y); }
__device__ __forceinline__ float2 cmul(float2 a, float2 b){ return make_float2(a.x*b.x - a.y*b.y, a.x*b.y + a.y*b.x); }
// a * conj(b)
__device__ __forceinline__ float2 cmulc(float2 a, float2 b){ return make_float2(a.x*b.x + a.y*b.y, a.y*b.x - a.x*b.y); }
__device__ __forceinline__ float2 csqr(float2 a){ return make_float2(a.x*a.x - a.y*a.y, 2.0f*a.x*a.y); }

// DIF butterfly: (a,b) -> (a+b, (a-b)*w)
__device__ __forceinline__ void bf_dif(float2& a, float2& b, float2 w){
    float2 t = csub(a, b); a = cadd(a, b); b = cmul(t, w);
}
// DIT (inverse) butterfly with conjugated twiddle: t=b*conj(w); (a,b) -> (a+t, a-t)
__device__ __forceinline__ void bf_dit(float2& a, float2& b, float2 w){
    float2 t = cmulc(b, w); b = csub(a, t); a = cadd(a, t);
}

// 4 local DIF radix-2 stages among 16 register-resident elements.
// wb[j] = twiddle base for this level; higher stages use squares of the base.
__device__ __forceinline__ void level_fwd(float2 r[16], const float2 wb[8]) {
    #pragma unroll
    for (int k = 0; k < 8; ++k) bf_dif(r[k], r[k+8], wb[k]);
    float2 w2[4];
    #pragma unroll
    for (int j = 0; j < 4; ++j) {
        w2[j] = csqr(wb[j]);
        bf_dif(r[j],   r[j+4],  w2[j]);
        bf_dif(r[j+8], r[j+12], w2[j]);
    }
    float2 w4[2];
    #pragma unroll
    for (int j = 0; j < 2; ++j) {
        w4[j] = csqr(w2[j]);
        bf_dif(r[j],    r[j+2],  w4[j]);
        bf_dif(r[j+4],  r[j+6],  w4[j]);
        bf_dif(r[j+8],  r[j+10], w4[j]);
        bf_dif(r[j+12], r[j+14], w4[j]);
    }
    float2 w8 = csqr(w4[0]);
    #pragma unroll
    for (int k = 0; k < 16; k += 2) bf_dif(r[k], r[k+1], w8);
}

// Mirror: 4 local DIT stages (inverse), conjugated twiddles inside bf_dit.
__device__ __forceinline__ void level_inv(float2 r[16], const float2 wb[8]) {
    float2 w2[4];
    #pragma unroll
    for (int j = 0; j < 4; ++j) w2[j] = csqr(wb[j]);
    float2 w4[2];
    w4[0] = csqr(w2[0]); w4[1] = csqr(w2[1]);
    float2 w8 = csqr(w4[0]);
    #pragma unroll
    for (int k = 0; k < 16; k += 2) bf_dit(r[k], r[k+1], w8);
    #pragma unroll
    for (int j = 0; j < 2; ++j) {
        bf_dit(r[j],    r[j+2],  w4[j]);
        bf_dit(r[j+4],  r[j+6],  w4[j]);
        bf_dit(r[j+8],  r[j+10], w4[j]);
        bf_dit(r[j+12], r[j+14], w4[j]);
    }
    #pragma unroll
    for (int j = 0; j < 4; ++j) {
        bf_dit(r[j],   r[j+4],  w2[j]);
        bf_dit(r[j+8], r[j+12], w2[j]);
    }
    #pragma unroll
    for (int k = 0; k < 8; ++k) bf_dit(r[k], r[k+8], wb[k]);
}

// Final DIF stage (half=1, w=1): partner is adjacent thread, element-wise over k.
__device__ __forceinline__ void shfl_stage(float2 r[16], int t) {
    const float sgn = (t & 1) ? -1.0f : 1.0f;
    #pragma unroll
    for (int k = 0; k < 16; ++k) {
        float ox = __shfl_xor_sync(0xffffffffu, r[k].x, 1);
        float oy = __shfl_xor_sync(0xffffffffu, r[k].y, 1);
        r[k].x = ox + sgn * r[k].x;
        r[k].y = oy + sgn * r[k].y;
    }
}

// Forward FFT: input in level-1 layout (r[k] = x[t + 512k], natural order),
// output in scrambled (t,k) layout (consistent with g_khat storage).
__device__ __forceinline__ void fft8192_fwd(float2 r[16], float2* sm, int t) {
    float2 wb[8];
    #pragma unroll
    for (int j = 0; j < 8; ++j) wb[j] = g_tw[t + 512*j];
    level_fwd(r, wb);                                      // half = 4096..512

    // exchange 1: stride-512 ownership -> stride-32 within 512-blocks
    #pragma unroll
    for (int k = 0; k < 16; ++k) sm[PD(t + 512*k)] = r[k];
    __syncthreads();
    {
        const int base = 512*(t >> 5) + (t & 31);
        #pragma unroll
        for (int k = 0; k < 16; ++k) r[k] = sm[PD(base + 32*k)];
    }
    #pragma unroll
    for (int j = 0; j < 8; ++j) wb[j] = g_tw16[(t & 31) + 32*j];
    level_fwd(r, wb);                                      // half = 256..32

    // exchange 2: stride-32 -> stride-2 within 32-blocks
    __syncthreads();
    {
        const int base = 512*(t >> 5) + (t & 31);
        #pragma unroll
        for (int k = 0; k < 16; ++k) sm[PD(base + 32*k)] = r[k];
    }
    __syncthreads();
    {
        const int base = 512*(t >> 5) + 32*((t >> 1) & 15) + (t & 1);
        #pragma unroll
        for (int k = 0; k < 16; ++k) r[k] = sm[PD(base + 2*k)];
    }
    #pragma unroll
    for (int j = 0; j < 8; ++j) wb[j] = g_tw256[(t & 1) + 2*j];
    level_fwd(r, wb);                                      // half = 16..2
    shfl_stage(r, t);                                      // half = 1
}

// Inverse FFT (unscaled): consumes the scrambled layout, returns natural order
// in level-1 layout (r[k] = L * x[t + 512k]).
__device__ __forceinline__ void fft8192_inv(float2 r[16], float2* sm, int t) {
    shfl_stage(r, t);                                      // half = 1
    float2 wb[8];
    #pragma unroll
    for (int j = 0; j < 8; ++j) wb[j] = g_tw256[(t & 1) + 2*j];
    level_inv(r, wb);                                      // half = 2..16

    __syncthreads();
    {
        const int base = 512*(t >> 5) + 32*((t >> 1) & 15) + (t & 1);
        #pragma unroll
        for (int k = 0; k < 16; ++k) sm[PD(base + 2*k)] = r[k];
    }
    __syncthreads();
    {
        const int base = 512*(t >> 5) + (t & 31);
        #pragma unroll
        for (int k = 0; k < 16; ++k) r[k] = sm[PD(base + 32*k)];
    }
    #pragma unroll
    for (int j = 0; j < 8; ++j) wb[j] = g_tw16[(t & 31) + 32*j];
    level_inv(r, wb);                                      // half = 32..256

    __syncthreads();
    {
        const int base = 512*(t >> 5) + (t & 31);
        #pragma unroll
        for (int k = 0; k < 16; ++k) sm[PD(base + 32*k)] = r[k];
    }
    __syncthreads();
    #pragma unroll
    for (int k = 0; k < 16; ++k) r[k] = sm[PD(t + 512*k)];
    #pragma unroll
    for (int j = 0; j < 8; ++j) wb[j] = g_tw[t + 512*j];
    level_inv(r, wb);                                      // half = 512..4096
}

__global__ void tw_kernel() {
    int j = blockIdx.x * blockDim.x + threadIdx.x;
    if (j < LEN/2) {
        float2 w; sincospif(-(float)j / 4096.0f, &w.y, &w.x); g_tw[j] = w;
    }
    if (j < 256) {
        float2 w; sincospif(-(float)(16*j) / 4096.0f, &w.y, &w.x); g_tw16[j] = w;
    }
    if (j < 16) {
        float2 w; sincospif(-(float)(256*j) / 4096.0f, &w.y, &w.x); g_tw256[j] = w;
    }
}

__global__ void __launch_bounds__(NT, 2) khat_kernel(const float* __restrict__ K) {
    extern __shared__ float2 sm[];
    const int h = blockIdx.x;
    const int t = threadIdx.x;
    const float* krow = K + (size_t)h * LEN;
    float2 r[16];
    #pragma unroll
    for (int k = 0; k < 16; ++k) r[k] = make_float2(krow[t + 512*k], 0.0f);
    fft8192_fwd(r, sm, t);
    float2* out = g_khat + (size_t)h * LEN + (size_t)t * 16;
    #pragma unroll
    for (int k = 0; k < 16; ++k) out[k] = r[k];
}

__global__ void __launch_bounds__(NT, 2) conv_kernel(const float* __restrict__ u,
                                                     const float* __restrict__ D,
                                                     float* __restrict__ y) {
    extern __shared__ float2 sm[];
    const int bid = blockIdx.x;          // [0, (BN/2)*HN)
    const int h   = bid & (HN - 1);
    const int bp  = bid >> 8;            // batch-pair index
    const int t   = threadIdx.x;

    const size_t row0 = ((size_t)(2*bp) * HN + h) * LEN;
    const size_t row1 = row0 + (size_t)HN * LEN;
    const float* u0 = u + row0;
    const float* u1 = u + row1;

    float2 r[16];
    #pragma unroll
    for (int k = 0; k < 16; ++k)
        r[k] = make_float2(u0[t + 512*k], u1[t + 512*k]);

    fft8192_fwd(r, sm, t);

    // pointwise multiply with K spectrum (same (t,k) layout -> coalesced 128B/thread)
    {
        const float2* kh = g_khat + (size_t)h * LEN + (size_t)t * 16;
        #pragma unroll
        for (int k = 0; k < 16; ++k) r[k] = cmul(r[k], kh[k]);
    }

    fft8192_inv(r, sm, t);

    const float dv   = D[h];
    const float invL = 1.0f / (float)LEN;
    float* y0 = y + row0;
    float* y1 = y + row1;
    #pragma unroll
    for (int k = 0; k < 16; ++k) {
        const int idx = t + 512*k;
        y0[idx] = tanhf(r[k].x * invL + dv * u0[idx]);
        y1[idx] = tanhf(r[k].y * invL + dv * u1[idx]);
    }
}

extern "C" void kernel_launch(void* const* d_in, const int* in_sizes, int n_in,
                              void* d_out, int out_size) {
    const float* u = (const float*)d_in[0];   // (B,H,L)
    const float* K = (const float*)d_in[1];   // (H,L)
    const float* D = (const float*)d_in[2];   // (H,)
    float* y = (float*)d_out;                 // (B,H,L)

    const int smem = PD(LEN) * sizeof(float2);   // 8448 float2 = 67584 B
    cudaFuncSetAttribute(khat_kernel, cudaFuncAttributeMaxDynamicSharedMemorySize, smem);
    cudaFuncSetAttribute(conv_kernel, cudaFuncAttributeMaxDynamicSharedMemorySize, smem);

    tw_kernel<<<(LEN/2 + NT - 1) / NT, NT>>>();
    khat_kernel<<<HN, NT, smem>>>(K);
    conv_kernel<<<(BN/2) * HN, NT, smem>>>(u, D, y);
}

// round 3
// speedup vs baseline: 1.9018x; 1.1976x over previous
#include <cuda_runtime.h>
#include <math.h>

#define LEN    8192
#define LOG2L  13
#define NT     512
#define HN     256
#define BN     8
#define PD(i)  ((i) + ((i) >> 5))  // smem padding: +1 float2 per 32

// K spectra (skip D folded in) in (thread,reg) layout + compact twiddle tables
__device__ float2 g_khat[(size_t)HN * LEN];   // 16 MB
__device__ float2 g_tw[LEN / 2];              // exp(-2*pi*i*j/8192), j<4096
__device__ float2 g_tw16[256];                // exp(-2*pi*i*16j/8192)
__device__ float2 g_tw256[16];                // exp(-2*pi*i*256j/8192)

__device__ __forceinline__ float2 cadd(float2 a, float2 b){ return make_float2(a.x+b.x, a.y+b.y); }
__device__ __forceinline__ float2 csub(float2 a, float2 b){ return make_float2(a.x-b.x, a.y-b.y); }
__device__ __forceinline__ float2 cmul(float2 a, float2 b){ return make_float2(a.x*b.x - a.y*b.y, a.x*b.y + a.y*b.x); }
__device__ __forceinline__ float2 cmulc(float2 a, float2 b){ return make_float2(a.x*b.x + a.y*b.y, a.y*b.x - a.x*b.y); }
__device__ __forceinline__ float2 csqr(float2 a){ return make_float2(a.x*a.x - a.y*a.y, 2.0f*a.x*a.y); }

__device__ __forceinline__ void bf_dif(float2& a, float2& b, float2 w){
    float2 t = csub(a, b); a = cadd(a, b); b = cmul(t, w);
}
__device__ __forceinline__ void bf_dit(float2& a, float2& b, float2 w){
    float2 t = cmulc(b, w); b = csub(a, t); a = cadd(a, t);
}

__device__ __forceinline__ float fast_tanh(float x){
    float e = __expf(2.0f * x);
    return 1.0f - __fdividef(2.0f, e + 1.0f);
}

// 4 local DIF stages among 16 register elements; lazy twiddle loads (keep only 4).
__device__ __forceinline__ void level_fwd(float2 r[16], const float2* __restrict__ tw,
                                          int off, int step) {
    float2 w2[4];
    #pragma unroll
    for (int k = 0; k < 8; ++k) {
        float2 w = tw[off + step*k];
        if (k < 4) w2[k] = w;
        bf_dif(r[k], r[k+8], w);
    }
    #pragma unroll
    for (int j = 0; j < 4; ++j) {
        w2[j] = csqr(w2[j]);
        bf_dif(r[j],   r[j+4],  w2[j]);
        bf_dif(r[j+8], r[j+12], w2[j]);
    }
    float2 w4[2] = { csqr(w2[0]), csqr(w2[1]) };
    #pragma unroll
    for (int j = 0; j < 2; ++j) {
        bf_dif(r[j],    r[j+2],  w4[j]);
        bf_dif(r[j+4],  r[j+6],  w4[j]);
        bf_dif(r[j+8],  r[j+10], w4[j]);
        bf_dif(r[j+12], r[j+14], w4[j]);
    }
    float2 w8 = csqr(w4[0]);
    #pragma unroll
    for (int k = 0; k < 16; k += 2) bf_dif(r[k], r[k+1], w8);
}

// Mirror: 4 local DIT (inverse) stages; twiddles re-loaded for the last stage.
__device__ __forceinline__ void level_inv(float2 r[16], const float2* __restrict__ tw,
                                          int off, int step) {
    float2 w2[4];
    #pragma unroll
    for (int j = 0; j < 4; ++j) w2[j] = csqr(tw[off + step*j]);
    float2 w4[2] = { csqr(w2[0]), csqr(w2[1]) };
    float2 w8 = csqr(w4[0]);
    #pragma unroll
    for (int k = 0; k < 16; k += 2) bf_dit(r[k], r[k+1], w8);
    #pragma unroll
    for (int j = 0; j < 2; ++j) {
        bf_dit(r[j],    r[j+2],  w4[j]);
        bf_dit(r[j+4],  r[j+6],  w4[j]);
        bf_dit(r[j+8],  r[j+10], w4[j]);
        bf_dit(r[j+12], r[j+14], w4[j]);
    }
    #pragma unroll
    for (int j = 0; j < 4; ++j) {
        bf_dit(r[j],   r[j+4],  w2[j]);
        bf_dit(r[j+8], r[j+12], w2[j]);
    }
    #pragma unroll
    for (int k = 0; k < 8; ++k) {
        float2 w = tw[off + step*k];
        bf_dit(r[k], r[k+8], w);
    }
}

// Final DIF stage (half=1, w=1): partner is the adjacent lane.
__device__ __forceinline__ void shfl_stage(float2 r[16], int t) {
    const float sgn = (t & 1) ? -1.0f : 1.0f;
    #pragma unroll
    for (int k = 0; k < 16; ++k) {
        float ox = __shfl_xor_sync(0xffffffffu, r[k].x, 1);
        float oy = __shfl_xor_sync(0xffffffffu, r[k].y, 1);
        r[k].x = ox + sgn * r[k].x;
        r[k].y = oy + sgn * r[k].y;
    }
}

// Forward FFT: natural-order input in r[k] = x[t+512k]; scrambled (t,k) output.
// Exchange 1 is block-wide (1 syncthreads); exchange 2 is warp-local.
__device__ __forceinline__ void fft8192_fwd(float2 r[16], float2* sm, int t) {
    level_fwd(r, g_tw, t, 512);                        // half 4096..512

    #pragma unroll
    for (int k = 0; k < 16; ++k) sm[PD(t + 512*k)] = r[k];
    __syncthreads();
    const int base1 = 512*(t >> 5) + (t & 31);
    #pragma unroll
    for (int k = 0; k < 16; ++k) r[k] = sm[PD(base1 + 32*k)];
    level_fwd(r, g_tw16, (t & 31), 32);                // half 256..32

    __syncwarp();
    #pragma unroll
    for (int k = 0; k < 16; ++k) sm[PD(base1 + 32*k)] = r[k];
    __syncwarp();
    const int base2 = 512*(t >> 5) + 32*((t >> 1) & 15) + (t & 1);
    #pragma unroll
    for (int k = 0; k < 16; ++k) r[k] = sm[PD(base2 + 2*k)];
    level_fwd(r, g_tw256, (t & 1), 2);                 // half 16..2
    shfl_stage(r, t);                                  // half 1
}

// Inverse FFT (unscaled): scrambled input -> natural order r[k] = L*x[t+512k].
__device__ __forceinline__ void fft8192_inv(float2 r[16], float2* sm, int t) {
    shfl_stage(r, t);                                  // half 1
    level_inv(r, g_tw256, (t & 1), 2);                 // half 2..16

    const int base2 = 512*(t >> 5) + 32*((t >> 1) & 15) + (t & 1);
    const int base1 = 512*(t >> 5) + (t & 31);
    __syncwarp();
    #pragma unroll
    for (int k = 0; k < 16; ++k) sm[PD(base2 + 2*k)] = r[k];
    __syncwarp();
    #pragma unroll
    for (int k = 0; k < 16; ++k) r[k] = sm[PD(base1 + 32*k)];
    level_inv(r, g_tw16, (t & 31), 32);                // half 32..256

    __syncwarp();
    #pragma unroll
    for (int k = 0; k < 16; ++k) sm[PD(base1 + 32*k)] = r[k];
    __syncthreads();
    #pragma unroll
    for (int k = 0; k < 16; ++k) r[k] = sm[PD(t + 512*k)];
    level_inv(r, g_tw, t, 512);                        // half 512..4096
}

__global__ void tw_kernel() {
    int j = blockIdx.x * blockDim.x + threadIdx.x;
    if (j < LEN/2) {
        float2 w; sincospif(-(float)j / 4096.0f, &w.y, &w.x); g_tw[j] = w;
    }
    if (j < 256) {
        float2 w; sincospif(-(float)(16*j) / 4096.0f, &w.y, &w.x); g_tw16[j] = w;
    }
    if (j < 16) {
        float2 w; sincospif(-(float)(256*j) / 4096.0f, &w.y, &w.x); g_tw256[j] = w;
    }
}

// K_hat[h] = FFT(K[h]) + D[h]  (skip connection folded into the spectrum)
__global__ void __launch_bounds__(NT, 2) khat_kernel(const float* __restrict__ K,
                                                     const float* __restrict__ D) {
    extern __shared__ float2 sm[];
    const int h = blockIdx.x;
    const int t = threadIdx.x;
    const float* krow = K + (size_t)h * LEN;
    float2 r[16];
    #pragma unroll
    for (int k = 0; k < 16; ++k) r[k] = make_float2(krow[t + 512*k], 0.0f);
    fft8192_fwd(r, sm, t);
    const float dv = D[h];
    float2* out = g_khat + (size_t)h * LEN + (size_t)t * 16;
    #pragma unroll
    for (int k = 0; k < 16; ++k) out[k] = make_float2(r[k].x + dv, r[k].y);
}

__global__ void __launch_bounds__(NT, 2) conv_kernel(const float* __restrict__ u,
                                                     float* __restrict__ y) {
    extern __shared__ float2 sm[];
    const int bid = blockIdx.x;          // [0, (BN/2)*HN)
    const int h   = bid & (HN - 1);
    const int bp  = bid >> 8;            // batch-pair index
    const int t   = threadIdx.x;

    const size_t row0 = ((size_t)(2*bp) * HN + h) * LEN;
    const size_t row1 = row0 + (size_t)HN * LEN;
    const float* u0 = u + row0;
    const float* u1 = u + row1;

    float2 r[16];
    #pragma unroll
    for (int k = 0; k < 16; ++k)
        r[k] = make_float2(u0[t + 512*k], u1[t + 512*k]);

    fft8192_fwd(r, sm, t);

    {   // pointwise multiply with (K_hat + D), same layout -> coalesced
        const float2* kh = g_khat + (size_t)h * LEN + (size_t)t * 16;
        #pragma unroll
        for (int k = 0; k < 16; ++k) r[k] = cmul(r[k], kh[k]);
    }

    fft8192_inv(r, sm, t);

    const float invL = 1.0f / (float)LEN;
    float* y0 = y + row0;
    float* y1 = y + row1;
    #pragma unroll
    for (int k = 0; k < 16; ++k) {
        const int idx = t + 512*k;
        y0[idx] = fast_tanh(r[k].x * invL);
        y1[idx] = fast_tanh(r[k].y * invL);
    }
}

extern "C" void kernel_launch(void* const* d_in, const int* in_sizes, int n_in,
                              void* d_out, int out_size) {
    const float* u = (const float*)d_in[0];   // (B,H,L)
    const float* K = (const float*)d_in[1];   // (H,L)
    const float* D = (const float*)d_in[2];   // (H,)
    float* y = (float*)d_out;                 // (B,H,L)

    const int smem = PD(LEN) * sizeof(float2);   // 8448 float2 = 67584 B
    cudaFuncSetAttribute(khat_kernel, cudaFuncAttributeMaxDynamicSharedMemorySize, smem);
    cudaFuncSetAttribute(conv_kernel, cudaFuncAttributeMaxDynamicSharedMemorySize, smem);

    tw_kernel<<<(LEN/2 + NT - 1) / NT, NT>>>();
    khat_kernel<<<HN, NT, smem>>>(K, D);
    conv_kernel<<<(BN/2) * HN, NT, smem>>>(u, y);
}

// round 4
// speedup vs baseline: 1.9558x; 1.0284x over previous
#include <cuda_runtime.h>
#include <math.h>

#define LEN    8192
#define NT     512
#define HN     256
#define BN     8
#define PD(i)  ((i) + ((i) >> 5))   // smem padding: +1 slot per 32

typedef unsigned long long u64;

// K spectra in broadcast form (skip D and 1/L folded in), packed twiddle tables.
// Table entry = ulonglong2{ wxx=(wx,wx), wyn=(-wy,wy) } (fwd) / { wxx, wyp=(wy,-wy) } (inv)
__device__ ulonglong2 g_khat[(size_t)HN * LEN];   // 32 MB
__device__ ulonglong2 g_T1f[4096], g_T1i[4096];   // level1: [k*512+p], m=index
__device__ ulonglong2 g_T2f[256],  g_T2i[256];    // level2: [k*32+p],  m=16*index
__device__ ulonglong2 g_T3f[16],   g_T3i[16];     // level3: [k*2+p],   m=256*index

// ---------- packed f32x2 helpers ----------
__device__ __forceinline__ u64 pk2(float x, float y){
    u64 r; asm("mov.b64 %0, {%1,%2};" : "=l"(r) : "f"(x), "f"(y)); return r;
}
__device__ __forceinline__ float2 upk(u64 v){
    float2 r; asm("mov.b64 {%0,%1}, %2;" : "=f"(r.x), "=f"(r.y) : "l"(v)); return r;
}
__device__ __forceinline__ u64 swp(u64 v){
    u64 r; asm("{\n .reg .f32 a,b;\n mov.b64 {a,b}, %1;\n mov.b64 %0, {b,a};\n}" : "=l"(r) : "l"(v));
    return r;
}
__device__ __forceinline__ u64 f2add(u64 a, u64 b){
    u64 r; asm("add.rn.f32x2 %0, %1, %2;" : "=l"(r) : "l"(a), "l"(b)); return r;
}
__device__ __forceinline__ u64 f2mul(u64 a, u64 b){
    u64 r; asm("mul.rn.f32x2 %0, %1, %2;" : "=l"(r) : "l"(a), "l"(b)); return r;
}
__device__ __forceinline__ u64 f2fma(u64 a, u64 b, u64 c){
    u64 r; asm("fma.rn.f32x2 %0, %1, %2, %3;" : "=l"(r) : "l"(a), "l"(b), "l"(c)); return r;
}
#define NEG1 0xBF800000BF800000ULL   // (-1.0f, -1.0f)

// DIF: a'=a+b; b'=(a-b)*w   (w given as broadcast wxx,wyn=(-wy,wy))
__device__ __forceinline__ void bf_fwd(u64& a, u64& b, u64 wxx, u64 wyn){
    u64 sum = f2add(a, b);
    u64 dif = f2fma(b, NEG1, a);
    b = f2fma(swp(dif), wyn, f2mul(dif, wxx));
    a = sum;
}
// DIT inverse: t=b*conj(w); a'=a+t; b'=a-t  (w given as wxx, wyp=(wy,-wy))
__device__ __forceinline__ void bf_inv(u64& a, u64& b, u64 wxx, u64 wyp){
    u64 t = f2fma(swp(b), wyp, f2mul(b, wxx));
    b = f2fma(t, NEG1, a);
    a = f2add(a, t);
}
// square twiddle in place, stays in broadcast form (works for both sign conventions)
__device__ __forceinline__ void csqr_pk(u64& xx, u64& yn){
    u64 t = f2mul(xx, xx);
    u64 s = f2mul(yn, yn);
    u64 m = f2mul(xx, yn);
    xx = f2fma(s, NEG1, t);
    yn = f2add(m, m);
}

__device__ __forceinline__ float fast_tanh(float x){
    float e = __expf(2.0f * x);
    return 1.0f - __fdividef(2.0f, e + 1.0f);
}

// ---------- 4 local stages (16 register elements) ----------
__device__ __forceinline__ void level_fwd_pk(u64 r[16], const ulonglong2* __restrict__ tab,
                                             int p, int P) {
    u64 xx[4], yn[4];
    #pragma unroll
    for (int k = 0; k < 8; ++k) {
        ulonglong2 w = tab[k*P + p];
        if (k < 4) { xx[k] = w.x; yn[k] = w.y; }
        bf_fwd(r[k], r[k+8], w.x, w.y);
    }
    #pragma unroll
    for (int j = 0; j < 4; ++j) {
        csqr_pk(xx[j], yn[j]);
        bf_fwd(r[j],   r[j+4],  xx[j], yn[j]);
        bf_fwd(r[j+8], r[j+12], xx[j], yn[j]);
    }
    #pragma unroll
    for (int j = 0; j < 2; ++j) {
        csqr_pk(xx[j], yn[j]);
        bf_fwd(r[j],    r[j+2],  xx[j], yn[j]);
        bf_fwd(r[j+4],  r[j+6],  xx[j], yn[j]);
        bf_fwd(r[j+8],  r[j+10], xx[j], yn[j]);
        bf_fwd(r[j+12], r[j+14], xx[j], yn[j]);
    }
    csqr_pk(xx[0], yn[0]);
    #pragma unroll
    for (int k = 0; k < 16; k += 2) bf_fwd(r[k], r[k+1], xx[0], yn[0]);
}

__device__ __forceinline__ void level_inv_pk(u64 r[16], const ulonglong2* __restrict__ tab,
                                             int p, int P) {
    u64 xx2[4], yn2[4];
    #pragma unroll
    for (int j = 0; j < 4; ++j) {
        ulonglong2 w = tab[j*P + p];
        xx2[j] = w.x; yn2[j] = w.y;
        csqr_pk(xx2[j], yn2[j]);                 // w^2
    }
    u64 xx4a = xx2[0], yn4a = yn2[0]; csqr_pk(xx4a, yn4a);   // w^4 (j=0)
    u64 xx4b = xx2[1], yn4b = yn2[1]; csqr_pk(xx4b, yn4b);   // w^4 (j=1)
    u64 xx8 = xx4a, yn8 = yn4a; csqr_pk(xx8, yn8);           // w^8
    #pragma unroll
    for (int k = 0; k < 16; k += 2) bf_inv(r[k], r[k+1], xx8, yn8);
    bf_inv(r[0],  r[2],  xx4a, yn4a);  bf_inv(r[4],  r[6],  xx4a, yn4a);
    bf_inv(r[8],  r[10], xx4a, yn4a);  bf_inv(r[12], r[14], xx4a, yn4a);
    bf_inv(r[1],  r[3],  xx4b, yn4b);  bf_inv(r[5],  r[7],  xx4b, yn4b);
    bf_inv(r[9],  r[11], xx4b, yn4b);  bf_inv(r[13], r[15], xx4b, yn4b);
    #pragma unroll
    for (int j = 0; j < 4; ++j) {
        bf_inv(r[j],   r[j+4],  xx2[j], yn2[j]);
        bf_inv(r[j+8], r[j+12], xx2[j], yn2[j]);
    }
    #pragma unroll
    for (int k = 0; k < 8; ++k) {
        ulonglong2 w = tab[k*P + p];
        bf_inv(r[k], r[k+8], w.x, w.y);
    }
}

// Final stride-1 stage (w=1): partner is adjacent lane.
__device__ __forceinline__ void shfl_stage_pk(u64 r[16], int t) {
    const float sgn = (t & 1) ? -1.0f : 1.0f;
    #pragma unroll
    for (int k = 0; k < 16; ++k) {
        float2 v = upk(r[k]);
        float ox = __shfl_xor_sync(0xffffffffu, v.x, 1);
        float oy = __shfl_xor_sync(0xffffffffu, v.y, 1);
        r[k] = pk2(fmaf(sgn, v.x, ox), fmaf(sgn, v.y, oy));
    }
}

// Forward FFT: natural order r[k]=x[t+512k] -> scrambled (t,k) layout.
__device__ __forceinline__ void fft_fwd(u64 r[16], u64* sm, int t) {
    level_fwd_pk(r, g_T1f, t, 512);
    #pragma unroll
    for (int k = 0; k < 16; ++k) sm[PD(t + 512*k)] = r[k];
    __syncthreads();
    const int base1 = 512*(t >> 5) + (t & 31);
    #pragma unroll
    for (int k = 0; k < 16; ++k) r[k] = sm[PD(base1 + 32*k)];
    level_fwd_pk(r, g_T2f, t & 31, 32);
    __syncwarp();
    #pragma unroll
    for (int k = 0; k < 16; ++k) sm[PD(base1 + 32*k)] = r[k];
    __syncwarp();
    const int base2 = 512*(t >> 5) + 32*((t >> 1) & 15) + (t & 1);
    #pragma unroll
    for (int k = 0; k < 16; ++k) r[k] = sm[PD(base2 + 2*k)];
    level_fwd_pk(r, g_T3f, t & 1, 2);
    shfl_stage_pk(r, t);
}

// Inverse (unscaled): scrambled -> natural order r[k]=L*x[t+512k].
__device__ __forceinline__ void fft_inv(u64 r[16], u64* sm, int t) {
    shfl_stage_pk(r, t);
    level_inv_pk(r, g_T3i, t & 1, 2);
    const int base2 = 512*(t >> 5) + 32*((t >> 1) & 15) + (t & 1);
    const int base1 = 512*(t >> 5) + (t & 31);
    __syncwarp();
    #pragma unroll
    for (int k = 0; k < 16; ++k) sm[PD(base2 + 2*k)] = r[k];
    __syncwarp();
    #pragma unroll
    for (int k = 0; k < 16; ++k) r[k] = sm[PD(base1 + 32*k)];
    level_inv_pk(r, g_T2i, t & 31, 32);
    __syncwarp();
    #pragma unroll
    for (int k = 0; k < 16; ++k) sm[PD(base1 + 32*k)] = r[k];
    __syncthreads();
    #pragma unroll
    for (int k = 0; k < 16; ++k) r[k] = sm[PD(t + 512*k)];
    level_inv_pk(r, g_T1i, t, 512);
}

// Build broadcast twiddle tables. Layout [k*P+p] makes m = M*index for all levels.
__global__ void tw_kernel() {
    int i = blockIdx.x * blockDim.x + threadIdx.x;
    float2 w;
    if (i < 4096) {
        sincospif(-(float)i / 4096.0f, &w.y, &w.x);          // w = exp(-2*pi*i*m/8192), m=i
        g_T1f[i] = make_ulonglong2(pk2(w.x, w.x), pk2(-w.y, w.y));
        g_T1i[i] = make_ulonglong2(pk2(w.x, w.x), pk2(w.y, -w.y));
    }
    if (i < 256) {
        sincospif(-(float)(16*i) / 4096.0f, &w.y, &w.x);
        g_T2f[i] = make_ulonglong2(pk2(w.x, w.x), pk2(-w.y, w.y));
        g_T2i[i] = make_ulonglong2(pk2(w.x, w.x), pk2(w.y, -w.y));
    }
    if (i < 16) {
        sincospif(-(float)(256*i) / 4096.0f, &w.y, &w.x);
        g_T3f[i] = make_ulonglong2(pk2(w.x, w.x), pk2(-w.y, w.y));
        g_T3i[i] = make_ulonglong2(pk2(w.x, w.x), pk2(w.y, -w.y));
    }
}

// K_hat[h] = (FFT(K[h]) + D[h]) / L, stored in broadcast-cmul form.
__global__ void __launch_bounds__(NT, 2) khat_kernel(const float* __restrict__ K,
                                                     const float* __restrict__ D) {
    extern __shared__ u64 sm[];
    const int h = blockIdx.x;
    const int t = threadIdx.x;
    const float* krow = K + (size_t)h * LEN;
    u64 r[16];
    #pragma unroll
    for (int k = 0; k < 16; ++k) r[k] = pk2(krow[t + 512*k], 0.0f);
    fft_fwd(r, sm, t);
    const float dv = D[h];
    const float invL = 1.0f / (float)LEN;
    ulonglong2* out = g_khat + (size_t)h * LEN + (size_t)t * 16;
    #pragma unroll
    for (int k = 0; k < 16; ++k) {
        float2 v = upk(r[k]);
        float a = (v.x + dv) * invL;
        float b = v.y * invL;
        out[k] = make_ulonglong2(pk2(a, a), pk2(-b, b));
    }
}

__global__ void __launch_bounds__(NT, 2) conv_kernel(const float* __restrict__ u,
                                                     float* __restrict__ y) {
    extern __shared__ u64 sm[];
    const int bid = blockIdx.x;           // [0, (BN/2)*HN)
    const int h   = bid & (HN - 1);
    const int bp  = bid >> 8;             // batch-pair index
    const int t   = threadIdx.x;

    const size_t row0 = ((size_t)(2*bp) * HN + h) * LEN;
    const size_t row1 = row0 + (size_t)HN * LEN;
    const float* u0 = u + row0;
    const float* u1 = u + row1;

    u64 r[16];
    #pragma unroll
    for (int k = 0; k < 16; ++k)
        r[k] = pk2(u0[t + 512*k], u1[t + 512*k]);

    fft_fwd(r, sm, t);

    {   // pointwise product with (K_hat + D)/L in broadcast form
        const ulonglong2* kh = g_khat + (size_t)h * LEN + (size_t)t * 16;
        #pragma unroll
        for (int k = 0; k < 16; ++k) {
            ulonglong2 w = kh[k];
            r[k] = f2fma(swp(r[k]), w.y, f2mul(r[k], w.x));
        }
    }

    fft_inv(r, sm, t);

    float* y0 = y + row0;
    float* y1 = y + row1;
    #pragma unroll
    for (int k = 0; k < 16; ++k) {
        const int idx = t + 512*k;
        float2 v = upk(r[k]);
        y0[idx] = fast_tanh(v.x);
        y1[idx] = fast_tanh(v.y);
    }
}

extern "C" void kernel_launch(void* const* d_in, const int* in_sizes, int n_in,
                              void* d_out, int out_size) {
    const float* u = (const float*)d_in[0];   // (B,H,L)
    const float* K = (const float*)d_in[1];   // (H,L)
    const float* D = (const float*)d_in[2];   // (H,)
    float* y = (float*)d_out;                 // (B,H,L)

    const int smem = PD(LEN) * sizeof(u64);   // 8448 * 8 = 67584 B
    cudaFuncSetAttribute(khat_kernel, cudaFuncAttributeMaxDynamicSharedMemorySize, smem);
    cudaFuncSetAttribute(conv_kernel, cudaFuncAttributeMaxDynamicSharedMemorySize, smem);

    tw_kernel<<<8, NT>>>();
    khat_kernel<<<HN, NT, smem>>>(K, D);
    conv_kernel<<<(BN/2) * HN, NT, smem>>>(u, y);
}